// round 5
// baseline (speedup 1.0000x reference)
#include <cuda_runtime.h>
#include <cuda_bf16.h>
#include <cstdint>

// Problem dims (fixed by the reference)
#define NROWS   16384
#define INDIM   256
#define OUTDIM  128

// Tiling (stage 2)
#define BM 128
#define BK 32
#define S_STAGES 5
#define A_STRIDE 36    // [row][k] padded stride (floats), conflict-free frag loads
#define B_STRIDE 136   // [k][n]  padded stride (floats), conflict-free frag loads
#define A_STAGE_FLOATS (BM * A_STRIDE)   // 4608
#define B_STAGE_FLOATS (BK * B_STRIDE)   // 4352

// Intermediate h = x @ W^T + b, [NROWS][OUTDIM] row-major, values pre-rounded tf32-RN
__device__ float g_h[(size_t)NROWS * OUTDIM];

// One dynamic-smem declaration for the whole TU.
extern __shared__ char dyn_smem[];

__device__ __forceinline__ uint32_t f2tf32_rn(float f) {
    uint32_t u;
    asm("cvt.rna.tf32.f32 %0, %1;" : "=r"(u) : "f"(f));
    return u;
}
__device__ __forceinline__ void mma_tf32(float c[4], const uint32_t a[4], const uint32_t b[2]) {
    asm volatile(
        "mma.sync.aligned.m16n8k8.row.col.f32.tf32.tf32.f32 "
        "{%0,%1,%2,%3}, {%4,%5,%6,%7}, {%8,%9}, {%0,%1,%2,%3};"
        : "+f"(c[0]), "+f"(c[1]), "+f"(c[2]), "+f"(c[3])
        : "r"(a[0]), "r"(a[1]), "r"(a[2]), "r"(a[3]), "r"(b[0]), "r"(b[1]));
}
__device__ __forceinline__ void cp_async16(uint32_t saddr, const float* g) {
    asm volatile("cp.async.cg.shared.global [%0], [%1], 16;" :: "r"(saddr), "l"(g));
}
__device__ __forceinline__ void cp_commit() { asm volatile("cp.async.commit_group;"); }
__device__ __forceinline__ uint32_t smem_u32(const void* p) {
    uint32_t a;
    asm("{ .reg .u64 t; cvta.to.shared.u64 t, %1; cvt.u32.u64 %0, t; }" : "=r"(a) : "l"(p));
    return a;
}

// ---- tile loaders -----------------------------------------------------------
// [128 rows x 32 k] row-major source -> smem [row][k] stride A_STRIDE. 1024 chunks.
template <int NT>
__device__ __forceinline__ void load_tile_rowmajor(uint32_t sbase, const float* src,
                                                   int row0, int k0, int ldK, int tid) {
#pragma unroll
    for (int t = 0; t < 1024 / NT; t++) {
        int idx = tid + t * NT;
        int r  = idx >> 3;
        int cc = (idx & 7) << 2;
        cp_async16(sbase + (uint32_t)(r * A_STRIDE + cc) * 4u,
                   src + (size_t)(row0 + r) * ldK + k0 + cc);
    }
}
// [32 k x 128 n] from row-major [K x 128] source -> smem [k][n] stride B_STRIDE.
template <int NT>
__device__ __forceinline__ void load_tile_kn(uint32_t sbase, const float* src,
                                             int k0, int tid) {
#pragma unroll
    for (int t = 0; t < 1024 / NT; t++) {
        int idx = tid + t * NT;
        int k = idx >> 5;
        int n = (idx & 31) << 2;
        cp_async16(sbase + (uint32_t)(k * B_STRIDE + n) * 4u,
                   src + (size_t)(k0 + k) * OUTDIM + n);
    }
}

// ============================================================================
// Stage 1: h = x @ W^T + b  (writes g_h, tf32-RN rounded)   ~1 GFLOP
// ============================================================================
__global__ __launch_bounds__(256, 1)
void gemm_lin(const float* __restrict__ x, const float* __restrict__ W,
              const float* __restrict__ bias) {
    float* smem = (float*)dyn_smem;
    float* As0 = smem;
    float* As1 = As0 + BM * A_STRIDE;
    float* Ws0 = As1 + BM * A_STRIDE;
    float* Ws1 = Ws0 + OUTDIM * A_STRIDE;

    const int tid  = threadIdx.x;
    const int lane = tid & 31, wid = tid >> 5;
    const int warpM = wid >> 2, warpN = wid & 3;
    const int bm = blockIdx.x;

    uint32_t sA0 = smem_u32(As0), sA1 = smem_u32(As1);
    uint32_t sW0 = smem_u32(Ws0), sW1 = smem_u32(Ws1);

    float c[4][4][4];
#pragma unroll
    for (int i = 0; i < 4; i++)
#pragma unroll
        for (int j = 0; j < 4; j++)
#pragma unroll
            for (int k = 0; k < 4; k++) c[i][j][k] = 0.0f;

    load_tile_rowmajor<256>(sA0, x, bm * BM, 0, INDIM, tid);
    load_tile_rowmajor<256>(sW0, W, 0, 0, INDIM, tid);
    cp_commit();

    const int KTL = INDIM / BK; // 8
    for (int kt = 0; kt < KTL; kt++) {
        asm volatile("cp.async.wait_group 0;" ::: "memory");
        __syncthreads();
        if (kt + 1 < KTL) {
            load_tile_rowmajor<256>(((kt + 1) & 1) ? sA1 : sA0, x, bm * BM, (kt + 1) * BK, INDIM, tid);
            load_tile_rowmajor<256>(((kt + 1) & 1) ? sW1 : sW0, W, 0, (kt + 1) * BK, INDIM, tid);
            cp_commit();
        }
        const float* As = (kt & 1) ? As1 : As0;
        const float* Ws = (kt & 1) ? Ws1 : Ws0;

#pragma unroll
        for (int kk = 0; kk < BK; kk += 8) {
            uint32_t af[4][4];
#pragma unroll
            for (int mi = 0; mi < 4; mi++) {
                int r  = warpM * 64 + mi * 16 + (lane >> 2);
                int cc = kk + (lane & 3);
                af[mi][0] = f2tf32_rn(As[r * A_STRIDE + cc]);
                af[mi][1] = f2tf32_rn(As[(r + 8) * A_STRIDE + cc]);
                af[mi][2] = f2tf32_rn(As[r * A_STRIDE + cc + 4]);
                af[mi][3] = f2tf32_rn(As[(r + 8) * A_STRIDE + cc + 4]);
            }
            uint32_t bf[4][2];
#pragma unroll
            for (int ni = 0; ni < 4; ni++) {
                int n = warpN * 32 + ni * 8 + (lane >> 2);
                int k = kk + (lane & 3);
                bf[ni][0] = f2tf32_rn(Ws[n * A_STRIDE + k]);
                bf[ni][1] = f2tf32_rn(Ws[n * A_STRIDE + k + 4]);
            }
#pragma unroll
            for (int mi = 0; mi < 4; mi++)
#pragma unroll
                for (int ni = 0; ni < 4; ni++) mma_tf32(c[mi][ni], af[mi], bf[ni]);
        }
        __syncthreads();
    }

    // Epilogue: bias add, round to tf32-RN, store g_h.
#pragma unroll
    for (int ni = 0; ni < 4; ni++) {
        int cn = warpN * 32 + ni * 8 + ((lane & 3) << 1);
        float2 bb = *(const float2*)(bias + cn);
#pragma unroll
        for (int mi = 0; mi < 4; mi++) {
            int r = bm * BM + warpM * 64 + mi * 16 + (lane >> 2);
            float2 v0 = make_float2(__uint_as_float(f2tf32_rn(c[mi][ni][0] + bb.x)),
                                    __uint_as_float(f2tf32_rn(c[mi][ni][1] + bb.y)));
            float2 v1 = make_float2(__uint_as_float(f2tf32_rn(c[mi][ni][2] + bb.x)),
                                    __uint_as_float(f2tf32_rn(c[mi][ni][3] + bb.y)));
            *(float2*)&g_h[(size_t)r * OUTDIM + cn]       = v0;
            *(float2*)&g_h[(size_t)(r + 8) * OUTDIM + cn] = v1;
        }
    }
}

// ============================================================================
// Stage 2: out = A_hat @ h.  512 threads, 16 warps = 2(M) x 4(N) x 2(K-split).
// Warp tile 64x32, each warp covers half of each BK=32 slice.
// ============================================================================
__global__ __launch_bounds__(512, 1)
void gemm_aggr(const float* __restrict__ A, float* __restrict__ out) {
    float* smem = (float*)dyn_smem;
    float* AsBase = smem;                              // S * 4608 floats
    float* BsBase = smem + S_STAGES * A_STAGE_FLOATS;  // S * 4352 floats

    const int tid  = threadIdx.x;
    const int lane = tid & 31, wid = tid >> 5;         // wid 0..15
    const int warpK = wid >> 3;                        // 0,1
    const int warpM = (wid >> 2) & 1;                  // 0,1
    const int warpN = wid & 3;                         // 0..3
    const int bm = blockIdx.x;

    const uint32_t sA = smem_u32(AsBase);
    const uint32_t sB = smem_u32(BsBase);

    float c[4][4][4];                                  // [mi][ni][frag]
#pragma unroll
    for (int i = 0; i < 4; i++)
#pragma unroll
        for (int j = 0; j < 4; j++)
#pragma unroll
            for (int k = 0; k < 4; k++) c[i][j][k] = 0.0f;

    // Prologue: tiles 0 .. S-2
#pragma unroll
    for (int t = 0; t < S_STAGES - 1; t++) {
        load_tile_rowmajor<512>(sA + (uint32_t)t * A_STAGE_FLOATS * 4u, A, bm * BM, t * BK, NROWS, tid);
        load_tile_kn<512>(sB + (uint32_t)t * B_STAGE_FLOATS * 4u, g_h, t * BK, tid);
        cp_commit();
    }

    const int KT = NROWS / BK;   // 512
    const int kb = warpK * 16;   // this warp's K-half within the tile
    int st  = 0;
    int wst = S_STAGES - 1;

    for (int kt = 0; kt < KT; kt++) {
        asm volatile("cp.async.wait_group %0;" :: "n"(S_STAGES - 2) : "memory");
        __syncthreads();

        const float* As = AsBase + st * A_STAGE_FLOATS;
        const float* Bs = BsBase + st * B_STAGE_FLOATS;

#pragma unroll
        for (int kk2 = 0; kk2 < 2; kk2++) {
            const int kk = kb + kk2 * 8;
            uint32_t af[4][4];
#pragma unroll
            for (int mi = 0; mi < 4; mi++) {
                int r  = warpM * 64 + mi * 16 + (lane >> 2);
                int cc = kk + (lane & 3);
                af[mi][0] = f2tf32_rn(As[r * A_STRIDE + cc]);
                af[mi][1] = f2tf32_rn(As[(r + 8) * A_STRIDE + cc]);
                af[mi][2] = f2tf32_rn(As[r * A_STRIDE + cc + 4]);
                af[mi][3] = f2tf32_rn(As[(r + 8) * A_STRIDE + cc + 4]);
            }
            uint32_t bf[4][2];
#pragma unroll
            for (int ni = 0; ni < 4; ni++) {
                int n = warpN * 32 + ni * 8 + (lane >> 2);
                int k = kk + (lane & 3);
                bf[ni][0] = __float_as_uint(Bs[k * B_STRIDE + n]);        // h already tf32-RN
                bf[ni][1] = __float_as_uint(Bs[(k + 4) * B_STRIDE + n]);
            }
#pragma unroll
            for (int mi = 0; mi < 4; mi++)
#pragma unroll
                for (int ni = 0; ni < 4; ni++) mma_tf32(c[mi][ni], af[mi], bf[ni]);
        }

        int nt = kt + S_STAGES - 1;
        if (nt < KT) {
            load_tile_rowmajor<512>(sA + (uint32_t)wst * A_STAGE_FLOATS * 4u, A, bm * BM, nt * BK, NROWS, tid);
            load_tile_kn<512>(sB + (uint32_t)wst * B_STAGE_FLOATS * 4u, g_h, nt * BK, tid);
        }
        cp_commit();

        if (++st  == S_STAGES) st  = 0;
        if (++wst == S_STAGES) wst = 0;
    }

    // ---- K-split reduction: warpK=1 -> smem -> warpK=0 adds ----
    asm volatile("cp.async.wait_group 0;" ::: "memory");
    __syncthreads();

    float* red = smem;  // reuse tile smem: 8 warps * 2048 floats = 64KB
    float4* cf4 = (float4*)&c[0][0][0];   // 16 float4 per thread
    if (warpK == 1) {
        float4* dst = (float4*)(red + (wid - 8) * 2048);
#pragma unroll
        for (int i = 0; i < 16; i++) dst[i * 32 + lane] = cf4[i];
    }
    __syncthreads();
    if (warpK == 0) {
        const float4* src = (const float4*)(red + wid * 2048);
#pragma unroll
        for (int i = 0; i < 16; i++) {
            float4 v = src[i * 32 + lane];
            cf4[i].x += v.x; cf4[i].y += v.y; cf4[i].z += v.z; cf4[i].w += v.w;
        }
        // Epilogue store
#pragma unroll
        for (int mi = 0; mi < 4; mi++)
#pragma unroll
            for (int ni = 0; ni < 4; ni++) {
                int r  = bm * BM + warpM * 64 + mi * 16 + (lane >> 2);
                int cn = warpN * 32 + ni * 8 + ((lane & 3) << 1);
                *(float2*)&out[(size_t)r * OUTDIM + cn] =
                    make_float2(c[mi][ni][0], c[mi][ni][1]);
                *(float2*)&out[(size_t)(r + 8) * OUTDIM + cn] =
                    make_float2(c[mi][ni][2], c[mi][ni][3]);
            }
    }
}

// Shared memory sizes (bytes)
static const int SMEM_LIN  = (2 * BM * A_STRIDE + 2 * OUTDIM * A_STRIDE) * 4;             // 73728
static const int SMEM_AGGR = (S_STAGES * A_STAGE_FLOATS + S_STAGES * B_STAGE_FLOATS) * 4; // 179200

extern "C" void kernel_launch(void* const* d_in, const int* in_sizes, int n_in,
                              void* d_out, int out_size) {
    const float* x     = (const float*)d_in[0];
    const float* A_hat = (const float*)d_in[1];
    const float* W     = (const float*)d_in[2];
    const float* b     = (const float*)d_in[3];
    float* out = (float*)d_out;

    cudaFuncSetAttribute(gemm_lin,  cudaFuncAttributeMaxDynamicSharedMemorySize, SMEM_LIN);
    cudaFuncSetAttribute(gemm_aggr, cudaFuncAttributeMaxDynamicSharedMemorySize, SMEM_AGGR);

    gemm_lin<<<NROWS / BM, 256, SMEM_LIN>>>(x, W, b);
    gemm_aggr<<<NROWS / BM, 512, SMEM_AGGR>>>(A_hat, out);
}

// round 6
// speedup vs baseline: 1.0634x; 1.0634x over previous
#include <cuda_runtime.h>
#include <cuda_fp16.h>
#include <cuda_bf16.h>
#include <cstdint>
#include <cstring>

// Problem dims (fixed by the reference)
#define NROWS   16384
#define INDIM   256
#define OUTDIM  128

// Stage-2 tiling
#define BM 128
#define BK 32
#define KT (NROWS / BK)      // 512

// smem (halfs): bufA[2] stride-40 rows (128x32), bufB[2] interleaved 16x264
#define A_BUF_HALFS 5120     // 128 * 40
#define B_BUF_HALFS 4224     // 16 * 264
#define SMEM_AGGR ((2 * A_BUF_HALFS + 2 * B_BUF_HALFS) * 2)   // 37376 B

// Intermediate h in fp16, k-pair interleaved:
//   g_h2[(row>>1)*256 + col*2 + (row&1)]
__device__ __half g_h2[(size_t)NROWS * OUTDIM];

// One dynamic-smem declaration for the whole TU.
extern __shared__ char dyn_smem[];

// ---------------------------------------------------------------------------
__device__ __forceinline__ uint32_t smem_u32(const void* p) {
    uint32_t a;
    asm("{ .reg .u64 t; cvta.to.shared.u64 t, %1; cvt.u32.u64 %0, t; }" : "=r"(a) : "l"(p));
    return a;
}
__device__ __forceinline__ uint32_t f2tf32_rn(float f) {
    uint32_t u;
    asm("cvt.rna.tf32.f32 %0, %1;" : "=r"(u) : "f"(f));
    return u;
}
__device__ __forceinline__ void mma_tf32(float c[4], const uint32_t a[4], const uint32_t b[2]) {
    asm volatile(
        "mma.sync.aligned.m16n8k8.row.col.f32.tf32.tf32.f32 "
        "{%0,%1,%2,%3}, {%4,%5,%6,%7}, {%8,%9}, {%0,%1,%2,%3};"
        : "+f"(c[0]), "+f"(c[1]), "+f"(c[2]), "+f"(c[3])
        : "r"(a[0]), "r"(a[1]), "r"(a[2]), "r"(a[3]), "r"(b[0]), "r"(b[1]));
}
__device__ __forceinline__ void mma_f16(float c[4], const uint32_t a[4], const uint32_t b[2]) {
    asm volatile(
        "mma.sync.aligned.m16n8k16.row.col.f32.f16.f16.f32 "
        "{%0,%1,%2,%3}, {%4,%5,%6,%7}, {%8,%9}, {%0,%1,%2,%3};"
        : "+f"(c[0]), "+f"(c[1]), "+f"(c[2]), "+f"(c[3])
        : "r"(a[0]), "r"(a[1]), "r"(a[2]), "r"(a[3]), "r"(b[0]), "r"(b[1]));
}
__device__ __forceinline__ void cp_async16(uint32_t saddr, const void* g) {
    asm volatile("cp.async.cg.shared.global [%0], [%1], 16;" :: "r"(saddr), "l"(g));
}
__device__ __forceinline__ void cp_commit() { asm volatile("cp.async.commit_group;"); }

// ============================================================================
// Stage 1: h = x @ W^T + b  (tf32, RN both sides) -> g_h2 fp16 interleaved
// ============================================================================
#define A_STRIDE 36
__global__ __launch_bounds__(256, 1)
void gemm_lin(const float* __restrict__ x, const float* __restrict__ W,
              const float* __restrict__ bias) {
    float* smem = (float*)dyn_smem;
    float* As0 = smem;
    float* As1 = As0 + BM * A_STRIDE;
    float* Ws0 = As1 + BM * A_STRIDE;
    float* Ws1 = Ws0 + OUTDIM * A_STRIDE;

    const int tid  = threadIdx.x;
    const int lane = tid & 31, wid = tid >> 5;
    const int warpM = wid >> 2, warpN = wid & 3;
    const int bm = blockIdx.x;

    uint32_t sA0 = smem_u32(As0), sA1 = smem_u32(As1);
    uint32_t sW0 = smem_u32(Ws0), sW1 = smem_u32(Ws1);

    float c[4][4][4];
#pragma unroll
    for (int i = 0; i < 4; i++)
#pragma unroll
        for (int j = 0; j < 4; j++)
#pragma unroll
            for (int k = 0; k < 4; k++) c[i][j][k] = 0.0f;

    auto load36 = [&](uint32_t sbase, const float* src, int row0, int k0, int ldK) {
#pragma unroll
        for (int t = 0; t < 4; t++) {
            int idx = tid + t * 256;
            int r = idx >> 3, cc = (idx & 7) << 2;
            cp_async16(sbase + (uint32_t)(r * A_STRIDE + cc) * 4u,
                       src + (size_t)(row0 + r) * ldK + k0 + cc);
        }
    };

    load36(sA0, x, bm * BM, 0, INDIM);
    load36(sW0, W, 0, 0, INDIM);
    cp_commit();

    const int KTL = INDIM / BK; // 8
    for (int kt = 0; kt < KTL; kt++) {
        asm volatile("cp.async.wait_group 0;" ::: "memory");
        __syncthreads();
        if (kt + 1 < KTL) {
            load36(((kt + 1) & 1) ? sA1 : sA0, x, bm * BM, (kt + 1) * BK, INDIM);
            load36(((kt + 1) & 1) ? sW1 : sW0, W, 0, (kt + 1) * BK, INDIM);
            cp_commit();
        }
        const float* As = (kt & 1) ? As1 : As0;
        const float* Ws = (kt & 1) ? Ws1 : Ws0;

#pragma unroll
        for (int kk = 0; kk < BK; kk += 8) {
            uint32_t af[4][4];
#pragma unroll
            for (int mi = 0; mi < 4; mi++) {
                int r  = warpM * 64 + mi * 16 + (lane >> 2);
                int cc = kk + (lane & 3);
                af[mi][0] = f2tf32_rn(As[r * A_STRIDE + cc]);
                af[mi][1] = f2tf32_rn(As[(r + 8) * A_STRIDE + cc]);
                af[mi][2] = f2tf32_rn(As[r * A_STRIDE + cc + 4]);
                af[mi][3] = f2tf32_rn(As[(r + 8) * A_STRIDE + cc + 4]);
            }
            uint32_t bf[4][2];
#pragma unroll
            for (int ni = 0; ni < 4; ni++) {
                int n = warpN * 32 + ni * 8 + (lane >> 2);
                int k = kk + (lane & 3);
                bf[ni][0] = f2tf32_rn(Ws[n * A_STRIDE + k]);
                bf[ni][1] = f2tf32_rn(Ws[n * A_STRIDE + k + 4]);
            }
#pragma unroll
            for (int mi = 0; mi < 4; mi++)
#pragma unroll
                for (int ni = 0; ni < 4; ni++) mma_tf32(c[mi][ni], af[mi], bf[ni]);
        }
        __syncthreads();
    }

    // Epilogue: bias add, fp16-RN, store into the k-pair-interleaved g_h2.
#pragma unroll
    for (int ni = 0; ni < 4; ni++) {
        int cn = warpN * 32 + ni * 8 + ((lane & 3) << 1);
        float2 bb = *(const float2*)(bias + cn);
#pragma unroll
        for (int mi = 0; mi < 4; mi++) {
            int r0 = bm * BM + warpM * 64 + mi * 16 + (lane >> 2);
            int r1 = r0 + 8;
            size_t b0 = (size_t)(r0 >> 1) * 256 + (r0 & 1);
            size_t b1 = (size_t)(r1 >> 1) * 256 + (r1 & 1);
            g_h2[b0 + (size_t)cn * 2]       = __float2half_rn(c[mi][ni][0] + bb.x);
            g_h2[b0 + (size_t)(cn + 1) * 2] = __float2half_rn(c[mi][ni][1] + bb.y);
            g_h2[b1 + (size_t)cn * 2]       = __float2half_rn(c[mi][ni][2] + bb.x);
            g_h2[b1 + (size_t)(cn + 1) * 2] = __float2half_rn(c[mi][ni][3] + bb.y);
        }
    }
}

// ============================================================================
// Stage 2: out = A_hat @ h, fp16 HMMA m16n8k16, on-the-fly fp32->fp16 for A.
// 256 threads, 8 warps = 2(M) x 4(N), warp tile 64x32, BK=32 (2 k16 steps).
// ============================================================================
struct ARegs { float4 v[4]; };   // 16 floats: rows (tid>>2) and (tid>>2)+64, 8 k each

__device__ __forceinline__ void ldgA(ARegs& ra, const float* __restrict__ A,
                                     int bm, int kt, int tid) {
    const int row = tid >> 2, kc = (tid & 3) * 8;
    const float* p = A + (size_t)(bm * BM + row) * NROWS + kt * BK + kc;
    ra.v[0] = *(const float4*)p;
    ra.v[1] = *(const float4*)(p + 4);
    const float* q = p + (size_t)64 * NROWS;
    ra.v[2] = *(const float4*)q;
    ra.v[3] = *(const float4*)(q + 4);
}

__device__ __forceinline__ void stsA(__half* bufA, const ARegs& ra, int tid) {
    const int row = tid >> 2, kc = (tid & 3) * 8;
#pragma unroll
    for (int s = 0; s < 2; s++) {
        const float* f = (const float*)&ra.v[s * 2];
        __half2 h[4];
#pragma unroll
        for (int j = 0; j < 4; j++) h[j] = __floats2half2_rn(f[2 * j], f[2 * j + 1]);
        uint4 u;
        memcpy(&u, h, 16);
        *(uint4*)&bufA[(row + s * 64) * 40 + kc] = u;
    }
}

__device__ __forceinline__ void cpB(uint32_t dstBase, int kt, int tid) {
    const int p0 = kt * 16;   // pair-row base
#pragma unroll
    for (int t = 0; t < 2; t++) {
        int c = tid + t * 256;
        int kp = c >> 5, j = c & 31;
        cp_async16(dstBase + (uint32_t)(kp * 264 + j * 8) * 2u,
                   g_h2 + (size_t)(p0 + kp) * 256 + j * 8);
    }
}

__device__ __forceinline__ void computeTile(const __half* bufA, const __half* bufB,
                                            float c[4][4][4], int lane,
                                            int warpM, int warpN) {
    uint32_t af[2][4][4], bf[2][4][2];
#pragma unroll
    for (int kk = 0; kk < 2; kk++) {
#pragma unroll
        for (int mi = 0; mi < 4; mi++) {
            int r = warpM * 64 + mi * 16 + (lane >> 2);
            int k = kk * 16 + (lane & 3) * 2;
            af[kk][mi][0] = *(const uint32_t*)&bufA[r * 40 + k];
            af[kk][mi][1] = *(const uint32_t*)&bufA[(r + 8) * 40 + k];
            af[kk][mi][2] = *(const uint32_t*)&bufA[r * 40 + k + 8];
            af[kk][mi][3] = *(const uint32_t*)&bufA[(r + 8) * 40 + k + 8];
        }
#pragma unroll
        for (int ni = 0; ni < 4; ni++) {
            int n  = warpN * 32 + ni * 8 + (lane >> 2);
            int kp = kk * 8 + (lane & 3);
            bf[kk][ni][0] = *(const uint32_t*)&bufB[kp * 264 + n * 2];
            bf[kk][ni][1] = *(const uint32_t*)&bufB[(kp + 4) * 264 + n * 2];
        }
    }
#pragma unroll
    for (int kk = 0; kk < 2; kk++)
#pragma unroll
        for (int mi = 0; mi < 4; mi++)
#pragma unroll
            for (int ni = 0; ni < 4; ni++) mma_f16(c[mi][ni], af[kk][mi], bf[kk][ni]);
}

__global__ __launch_bounds__(256, 1)
void gemm_aggr(const float* __restrict__ A, float* __restrict__ out) {
    __half* sm = (__half*)dyn_smem;
    __half* bufA[2] = { sm,                      sm + A_BUF_HALFS };
    __half* bufB[2] = { sm + 2 * A_BUF_HALFS,    sm + 2 * A_BUF_HALFS + B_BUF_HALFS };
    const uint32_t sB0 = smem_u32(bufB[0]);
    const uint32_t sB1 = smem_u32(bufB[1]);

    const int tid  = threadIdx.x;
    const int lane = tid & 31, wid = tid >> 5;
    const int warpM = wid >> 2, warpN = wid & 3;
    const int bm = blockIdx.x;

    float c[4][4][4];
#pragma unroll
    for (int i = 0; i < 4; i++)
#pragma unroll
        for (int j = 0; j < 4; j++)
#pragma unroll
            for (int k = 0; k < 4; k++) c[i][j][k] = 0.0f;

    // Prologue: tile0 into buf0, tile1 into regs, B0 prefetched.
    ARegs ra;
    ldgA(ra, A, bm, 0, tid);
    cpB(sB0, 0, tid);
    cp_commit();
    stsA(bufA[0], ra, tid);
    ldgA(ra, A, bm, 1, tid);
    asm volatile("cp.async.wait_group 0;" ::: "memory");
    __syncthreads();

    for (int kt = 0; kt < KT; kt++) {
        const int nt1 = (kt + 1 < KT) ? kt + 1 : KT - 1;
        const int nt2 = (kt + 2 < KT) ? kt + 2 : KT - 1;

        // Prefetch tile kt+1 into the other buffers (safe: all warps finished
        // reading them in iteration kt-1 before the trailing barrier).
        cpB((kt & 1) ? sB0 : sB1, nt1, tid);
        cp_commit();
        stsA(bufA[(kt + 1) & 1], ra, tid);
        ldgA(ra, A, bm, nt2, tid);

        // Compute tile kt (covers the cp.async latency of tile kt+1).
        computeTile(bufA[kt & 1], bufB[kt & 1], c, lane, warpM, warpN);

        asm volatile("cp.async.wait_group 0;" ::: "memory");
        __syncthreads();
    }

    // Epilogue
#pragma unroll
    for (int mi = 0; mi < 4; mi++)
#pragma unroll
        for (int ni = 0; ni < 4; ni++) {
            int r  = bm * BM + warpM * 64 + mi * 16 + (lane >> 2);
            int cn = warpN * 32 + ni * 8 + ((lane & 3) << 1);
            *(float2*)&out[(size_t)r * OUTDIM + cn] =
                make_float2(c[mi][ni][0], c[mi][ni][1]);
            *(float2*)&out[(size_t)(r + 8) * OUTDIM + cn] =
                make_float2(c[mi][ni][2], c[mi][ni][3]);
        }
}

static const int SMEM_LIN = (2 * BM * A_STRIDE + 2 * OUTDIM * A_STRIDE) * 4;  // 73728

extern "C" void kernel_launch(void* const* d_in, const int* in_sizes, int n_in,
                              void* d_out, int out_size) {
    const float* x     = (const float*)d_in[0];
    const float* A_hat = (const float*)d_in[1];
    const float* W     = (const float*)d_in[2];
    const float* b     = (const float*)d_in[3];
    float* out = (float*)d_out;

    cudaFuncSetAttribute(gemm_lin,  cudaFuncAttributeMaxDynamicSharedMemorySize, SMEM_LIN);
    cudaFuncSetAttribute(gemm_aggr, cudaFuncAttributeMaxDynamicSharedMemorySize, SMEM_AGGR);

    gemm_lin<<<NROWS / BM, 256, SMEM_LIN>>>(x, W, b);
    gemm_aggr<<<NROWS / BM, 256, SMEM_AGGR>>>(A_hat, out);
}